// round 13
// baseline (speedup 1.0000x reference)
#include <cuda_runtime.h>
#include <cuda_fp16.h>
#include <cstdint>

#define TSEQ   2048
#define BATCH  4
#define NHEAD  16
#define HD     128
#define DIM    2048
#define MROWS  (BATCH * TSEQ)   // 8192
#define KVDIM  (2 * DIM)        // 4096

// ---------------- scratch (allocation-free: __device__ globals) ----------------
__device__ __half g_X16 [(size_t)MROWS * DIM];    // enc fp16, later attention output
__device__ __half g_D16 [(size_t)MROWS * DIM];    // dec fp16
__device__ __half g_Wkv [(size_t)DIM * KVDIM];    // fp16 W_kv, native [K,N]
__device__ __half g_Wq  [(size_t)DIM * DIM];      // fp16 W_q
__device__ __half g_Wo  [(size_t)DIM * DIM];      // fp16 W_o
__device__ __half g_K16 [(size_t)MROWS * DIM];
__device__ __half g_V16 [(size_t)MROWS * DIM];
__device__ __half g_Qh  [(size_t)MROWS * DIM];

// ---------------- helpers ----------------
__device__ __forceinline__ uint32_t smem_u32(const void* p) {
    uint32_t a;
    asm("{ .reg .u64 t; cvta.to.shared.u64 t, %1; cvt.u32.u64 %0, t; }"
        : "=r"(a) : "l"(p));
    return a;
}
#define CP_ASYNC16(dst, src) \
    asm volatile("cp.async.cg.shared.global [%0], [%1], 16;" :: "r"(dst), "l"(src))

__device__ __forceinline__ void ldmatrix_x4(uint32_t* r, uint32_t addr) {
    asm volatile("ldmatrix.sync.aligned.m8n8.x4.shared.b16 {%0,%1,%2,%3}, [%4];"
                 : "=r"(r[0]), "=r"(r[1]), "=r"(r[2]), "=r"(r[3]) : "r"(addr));
}
__device__ __forceinline__ void ldmatrix_x4_trans(uint32_t* r, uint32_t addr) {
    asm volatile("ldmatrix.sync.aligned.m8n8.x4.trans.shared.b16 {%0,%1,%2,%3}, [%4];"
                 : "=r"(r[0]), "=r"(r[1]), "=r"(r[2]), "=r"(r[3]) : "r"(addr));
}
__device__ __forceinline__ void sts32(uint32_t a, uint32_t v) {
    asm volatile("st.shared.b32 [%0], %1;" :: "r"(a), "r"(v));
}
__device__ __forceinline__ void mma_fp16(float* d, const uint32_t* a, const uint32_t* b) {
    asm volatile(
        "mma.sync.aligned.m16n8k16.row.col.f32.f16.f16.f32 "
        "{%0,%1,%2,%3}, {%4,%5,%6,%7}, {%8,%9}, {%0,%1,%2,%3};"
        : "+f"(d[0]), "+f"(d[1]), "+f"(d[2]), "+f"(d[3])
        : "r"(a[0]), "r"(a[1]), "r"(a[2]), "r"(a[3]), "r"(b[0]), "r"(b[1]));
}

// fast exp2 on FMA pipe (t <= ~0)
__device__ __forceinline__ float exp2p(float t) {
    t = fmaxf(t, -126.f);
    float fi = floorf(t);
    float x = t - fi - 0.5f;
    float p = 0.001885630f;
    p = fmaf(p, x, 0.013602145f);
    p = fmaf(p, x, 0.078494717f);
    p = fmaf(p, x, 0.339731669f);
    p = fmaf(p, x, 0.980258143f);
    p = fmaf(p, x, 1.414213562f);
    int e = (int)fi;
    return __int_as_float(__float_as_int(p) + (e << 23));
}

// ---------------- fused conversion: all fp32 inputs -> fp16 buffers ----------------
#define N_ACT (MROWS * DIM / 4)          // 4194304 float4
#define N_WKV (DIM * KVDIM / 4)          // 2097152
#define N_W   (DIM * DIM / 4)            // 1048576
#define N_CONV_TOTAL (2 * N_ACT + N_WKV + 2 * N_W)

__global__ __launch_bounds__(256) void conv_all_kernel(
    const float* __restrict__ enc, const float* __restrict__ dec,
    const float* __restrict__ wkv, const float* __restrict__ wq,
    const float* __restrict__ wo,
    __half* __restrict__ x16, __half* __restrict__ d16,
    __half* __restrict__ wkv16, __half* __restrict__ wq16,
    __half* __restrict__ wo16)
{
    int i = blockIdx.x * 256 + threadIdx.x;
    if (i >= N_CONV_TOTAL) return;
    const float* src; __half* dst; int off;
    if (i < N_ACT)                          { src = enc; dst = x16;   off = i; }
    else if (i < 2 * N_ACT)                 { src = dec; dst = d16;   off = i - N_ACT; }
    else if (i < 2 * N_ACT + N_WKV)         { src = wkv; dst = wkv16; off = i - 2 * N_ACT; }
    else if (i < 2 * N_ACT + N_WKV + N_W)   { src = wq;  dst = wq16;  off = i - 2 * N_ACT - N_WKV; }
    else                                    { src = wo;  dst = wo16;  off = i - 2 * N_ACT - N_WKV - N_W; }
    float4 v = ((const float4*)src)[off];
    __half2* hp = (__half2*)(dst + (size_t)off * 4);
    hp[0] = __floats2half2_rn(v.x, v.y);
    hp[1] = __floats2half2_rn(v.z, v.w);
}

// ---------------- mma.sync GEMM (fp16, single pass), templated epilogue ----------------
// MODE 0: fp32 C = acc + bias; MODE 1: fp16 K/V split; MODE 2: fp16 scaled q
#define BKG      64
#define ROWB     144
#define BROWB    272
#define ATILE_B  (128 * ROWB)              // 18432
#define BTILE_B  (64 * BROWB)              // 17408
#define BUF_B    (ATILE_B + BTILE_B)       // 35840
#define GEMM_SMEM (2 * BUF_B)              // 71680 -> 2 CTAs/SM
#define NCH 32

template<int MODE>
__global__ __launch_bounds__(256, 2) void gemm_tc_kernel(
    const __half* __restrict__ Ah, const __half* __restrict__ Wf,
    const float* __restrict__ bias, void* outA, void* outB, int N)
{
    extern __shared__ char smem[];
    const uint32_t sbase = smem_u32(smem);
    const int tid  = threadIdx.x;
    const int wid  = tid >> 5;
    const int lane = tid & 31;
    const int wm   = wid & 1;
    const int wn   = wid >> 1;
    const int bm   = blockIdx.y * 128;
    const int bn   = blockIdx.x * 128;

    float acc[4][4][4];
#pragma unroll
    for (int i = 0; i < 4; i++)
#pragma unroll
        for (int j = 0; j < 4; j++)
#pragma unroll
            for (int k = 0; k < 4; k++) acc[i][j][k] = 0.f;

    const uint32_t a_lane_off = (uint32_t)((lane & 15) * ROWB + ((lane >> 4) << 3) * 2);
    const uint32_t a_warp_base = (uint32_t)(wm * 64) * ROWB;

    auto load_chunk = [&](int ci, int buf) {
        const int k0 = ci * BKG;
        const uint32_t base = sbase + (uint32_t)buf * BUF_B;
#pragma unroll
        for (int j = 0; j < 8; j++) {
            int c = j * 256 + tid;
            uint32_t dst;
            const __half* g;
            if (c < 1024) {
                int row = c >> 3, seg = c & 7;
                dst = base + (uint32_t)(row * ROWB + seg * 16);
                g = Ah + (size_t)(bm + row) * DIM + k0 + seg * 8;
            } else {
                int idx = c - 1024;
                int row = idx >> 4, seg = idx & 15;
                dst = base + (uint32_t)(ATILE_B + row * BROWB + seg * 16);
                g = Wf + (size_t)(k0 + row) * N + bn + seg * 8;
            }
            CP_ASYNC16(dst, g);
        }
        asm volatile("cp.async.commit_group;");
    };

    load_chunk(0, 0);

    for (int i = 0; i < NCH; i++) {
        const int b = i & 1;
        const bool has_next = (i + 1 < NCH);
        if (has_next) load_chunk(i + 1, b ^ 1);
        if (has_next) asm volatile("cp.async.wait_group 1;");
        else          asm volatile("cp.async.wait_group 0;");
        __syncthreads();

        const uint32_t abuf = sbase + (uint32_t)b * BUF_B;
        const uint32_t bbuf = abuf + ATILE_B;
#pragma unroll
        for (int ks = 0; ks < 4; ks++) {
            uint32_t afrag[4][4];
#pragma unroll
            for (int mf = 0; mf < 4; mf++)
                ldmatrix_x4(afrag[mf],
                            abuf + a_warp_base + (uint32_t)(mf * 16 * ROWB)
                                 + (uint32_t)(ks * 32) + a_lane_off);
            uint32_t bfrag[4][2];
#pragma unroll
            for (int p = 0; p < 2; p++) {
                uint32_t r4[4];
                ldmatrix_x4_trans(r4, bbuf
                    + (uint32_t)((ks * 16 + (lane & 15)) * BROWB
                                 + (wn * 32 + p * 16 + (lane >> 4) * 8) * 2));
                bfrag[2 * p + 0][0] = r4[0]; bfrag[2 * p + 0][1] = r4[1];
                bfrag[2 * p + 1][0] = r4[2]; bfrag[2 * p + 1][1] = r4[3];
            }
#pragma unroll
            for (int mf = 0; mf < 4; mf++)
#pragma unroll
                for (int nf = 0; nf < 4; nf++)
                    mma_fp16(acc[mf][nf], afrag[mf], bfrag[nf]);
        }
        __syncthreads();
    }

    // ---- epilogue ----
    const float CSCL = (float)(0.08838834764831845 * 1.4426950408889634);
    float2 bfr[4];
#pragma unroll
    for (int nf = 0; nf < 4; nf++) {
        int col = bn + wn * 32 + nf * 8 + (lane & 3) * 2;
        bfr[nf].x = __ldg(bias + col);
        bfr[nf].y = __ldg(bias + col + 1);
    }
#pragma unroll
    for (int mf = 0; mf < 4; mf++) {
#pragma unroll
        for (int h8 = 0; h8 < 2; h8++) {
            int row = bm + wm * 64 + mf * 16 + (lane >> 2) + h8 * 8;
#pragma unroll
            for (int nf = 0; nf < 4; nf++) {
                float vx = acc[mf][nf][2 * h8 + 0] + bfr[nf].x;
                float vy = acc[mf][nf][2 * h8 + 1] + bfr[nf].y;
                int coff = wn * 32 + nf * 8 + (lane & 3) * 2;
                if (MODE == 0) {
                    float* C = (float*)outA;
                    float2 o; o.x = vx; o.y = vy;
                    *(float2*)(C + (size_t)row * N + bn + coff) = o;
                } else if (MODE == 1) {
                    __half* dst = (bn < DIM) ? (__half*)outA : (__half*)outB;
                    int cb = (bn & (DIM - 1)) + coff;
                    *(__half2*)(dst + (size_t)row * DIM + cb) =
                        __floats2half2_rn(vx, vy);
                } else {
                    *(__half2*)((__half*)outA + (size_t)row * DIM + bn + coff) =
                        __floats2half2_rn(vx * CSCL, vy * CSCL);
                }
            }
        }
    }
}

// ---------------- fp16 tensor-core flash attention (BM=128, 512 threads) ----------------
#define SM_QH   0
#define SM_K0   34816
#define SM_K1   52224
#define SM_V    69632
#define SM_P    87040          // 128 x 144B
#define SM_RMAX 105472         // 128 x 2 floats
#define SM_RSUM 106496
#define ATT_SMEM 107520

__global__ __launch_bounds__(512, 1) void attn_tc_kernel(
    const __half* __restrict__ Qh,
    const __half* __restrict__ K16, const __half* __restrict__ V16,
    __half* __restrict__ OAh)
{
    extern __shared__ char smem[];
    const uint32_t sb = smem_u32(smem);
    const int tid = threadIdx.x, lane = tid & 31, wid = tid >> 5;
    const int wm = wid & 7, wn = wid >> 3;          // 8 M-warps x 2 N-warps
    const int qt = (int)gridDim.x - 1 - (int)blockIdx.x;  // heavy tiles first
    const int bh = blockIdx.y, bb = bh >> 4, hh = bh & 15;
    const int q0 = qt * 128;
    const int nj = 2 * qt + 2;                      // 64-key tiles to process
    const size_t rowbase = (size_t)bb * TSEQ;
    const int hoff = hh * HD;

    float* sRMax = (float*)(smem + SM_RMAX);
    float* sRSum = (float*)(smem + SM_RSUM);

    // Q tile: 128 rows x 128 halfs
#pragma unroll
    for (int it = 0; it < 4; it++) {
        int idx = tid + it * 512; int r = idx >> 4, sg = idx & 15;
        CP_ASYNC16(sb + SM_QH + r * 272 + sg * 16,
                   Qh + (rowbase + q0 + r) * DIM + hoff + sg * 8);
    }
    asm volatile("cp.async.commit_group;");

    auto loadK = [&](int j0, uint32_t base) {
#pragma unroll
        for (int it = 0; it < 2; it++) {
            int idx = tid + it * 512; int r = idx >> 4, sg = idx & 15;
            CP_ASYNC16(base + r * 272 + sg * 16,
                       K16 + (rowbase + j0 + r) * DIM + hoff + sg * 8);
        }
        asm volatile("cp.async.commit_group;");
    };
    auto loadV = [&](int j0) {
#pragma unroll
        for (int it = 0; it < 2; it++) {
            int idx = tid + it * 512; int r = idx >> 4, sg = idx & 15;
            CP_ASYNC16(sb + SM_V + r * 272 + sg * 16,
                       V16 + (rowbase + j0 + r) * DIM + hoff + sg * 8);
        }
        asm volatile("cp.async.commit_group;");
    };

    loadK(0, sb + SM_K0);

    float oacc[8][4];
#pragma unroll
    for (int i = 0; i < 8; i++)
#pragma unroll
        for (int k = 0; k < 4; k++) oacc[i][k] = 0.f;
    float m0 = -1e9f, m1 = -1e9f, l0 = 0.f, l1 = 0.f;

    const int r0 = wm * 16 + (lane >> 2);
    const int r1 = r0 + 8;
    int buf = 0;

    for (int j = 0; j < nj; j++) {
        const int j0 = j * 64;
        loadV(j0);
        if (j < nj - 1) loadK(j0 + 64, sb + (buf ? SM_K0 : SM_K1));
        if (j < nj - 1) asm volatile("cp.async.wait_group 2;");
        else            asm volatile("cp.async.wait_group 1;");
        __syncthreads();   // S1: Q + K[j] visible

        const uint32_t kb = sb + (buf ? SM_K1 : SM_K0);
        float sacc[4][4];
#pragma unroll
        for (int nf = 0; nf < 4; nf++)
#pragma unroll
            for (int e = 0; e < 4; e++) sacc[nf][e] = 0.f;

#pragma unroll
        for (int kc = 0; kc < 8; kc++) {
            uint32_t bbf[4][2];
#pragma unroll
            for (int p = 0; p < 2; p++) {
                uint32_t r4[4];
                int g = lane >> 3, r = lane & 7;
                ldmatrix_x4(r4, kb + (uint32_t)(
                    (wn * 32 + p * 16 + ((g >> 1) << 3) + r) * 272
                    + kc * 32 + ((g & 1) << 4)));
                bbf[2 * p + 0][0] = r4[0]; bbf[2 * p + 0][1] = r4[1];
                bbf[2 * p + 1][0] = r4[2]; bbf[2 * p + 1][1] = r4[3];
            }
            uint32_t qa = (uint32_t)((wm * 16 + (lane & 15)) * 272
                                     + kc * 32 + (lane >> 4) * 16);
            uint32_t ah[4];
            ldmatrix_x4(ah, sb + SM_QH + qa);
#pragma unroll
            for (int nf = 0; nf < 4; nf++)
                mma_fp16(sacc[nf], ah, bbf[nf]);
        }

        // causal mask: last two key tiles straddle the diagonal
        if (j >= nj - 2) {
#pragma unroll
            for (int nf = 0; nf < 4; nf++)
#pragma unroll
                for (int e = 0; e < 4; e++) {
                    int col = j0 + wn * 32 + nf * 8 + 2 * (lane & 3) + (e & 1);
                    int row = q0 + ((e >> 1) ? r1 : r0);
                    if (col > row) sacc[nf][e] = -1e9f;
                }
        }

        float mx0 = -1e30f, mx1 = -1e30f;
#pragma unroll
        for (int nf = 0; nf < 4; nf++) {
            mx0 = fmaxf(mx0, fmaxf(sacc[nf][0], sacc[nf][1]));
            mx1 = fmaxf(mx1, fmaxf(sacc[nf][2], sacc[nf][3]));
        }
        mx0 = fmaxf(mx0, __shfl_xor_sync(0xffffffffu, mx0, 1));
        mx0 = fmaxf(mx0, __shfl_xor_sync(0xffffffffu, mx0, 2));
        mx1 = fmaxf(mx1, __shfl_xor_sync(0xffffffffu, mx1, 1));
        mx1 = fmaxf(mx1, __shfl_xor_sync(0xffffffffu, mx1, 2));
        if ((lane & 3) == 0) {
            sRMax[r0 * 2 + wn] = mx0;
            sRMax[r1 * 2 + wn] = mx1;
        }
        __syncthreads();   // S2

        float nm0 = fmaxf(m0, fmaxf(sRMax[r0 * 2], sRMax[r0 * 2 + 1]));
        float nm1 = fmaxf(m1, fmaxf(sRMax[r1 * 2], sRMax[r1 * 2 + 1]));
        float alpha0 = exp2p(m0 - nm0);
        float alpha1 = exp2p(m1 - nm1);
        m0 = nm0; m1 = nm1;

        float s0 = 0.f, s1 = 0.f;
        uint32_t pbase = sb + SM_P + (uint32_t)((wm * 16 + (lane >> 2)) * 144
                                                + wn * 64 + (lane & 3) * 4);
#pragma unroll
        for (int nf = 0; nf < 4; nf++) {
            float p0 = exp2p(sacc[nf][0] - m0);
            float p1 = exp2p(sacc[nf][1] - m0);
            float p2 = exp2p(sacc[nf][2] - m1);
            float p3 = exp2p(sacc[nf][3] - m1);
            s0 += p0 + p1; s1 += p2 + p3;
            __half2 hp0 = __floats2half2_rn(p0, p1);
            __half2 hp1 = __floats2half2_rn(p2, p3);
            sts32(pbase + nf * 16,           *(uint32_t*)&hp0);
            sts32(pbase + nf * 16 + 8 * 144, *(uint32_t*)&hp1);
        }
        s0 += __shfl_xor_sync(0xffffffffu, s0, 1);
        s0 += __shfl_xor_sync(0xffffffffu, s0, 2);
        s1 += __shfl_xor_sync(0xffffffffu, s1, 1);
        s1 += __shfl_xor_sync(0xffffffffu, s1, 2);
        if ((lane & 3) == 0) {
            sRSum[r0 * 2 + wn] = s0;
            sRSum[r1 * 2 + wn] = s1;
        }

#pragma unroll
        for (int nb = 0; nb < 8; nb++) {
            oacc[nb][0] *= alpha0; oacc[nb][1] *= alpha0;
            oacc[nb][2] *= alpha1; oacc[nb][3] *= alpha1;
        }

        if (j < nj - 1) asm volatile("cp.async.wait_group 1;");
        else            asm volatile("cp.async.wait_group 0;");
        __syncthreads();   // S3: V + sP + sRSum visible

        l0 = l0 * alpha0 + sRSum[r0 * 2] + sRSum[r0 * 2 + 1];
        l1 = l1 * alpha1 + sRSum[r1 * 2] + sRSum[r1 * 2 + 1];

#pragma unroll
        for (int kc = 0; kc < 4; kc++) {
            uint32_t pa[4];
            ldmatrix_x4(pa, sb + SM_P + (uint32_t)((wm * 16 + (lane & 15)) * 144
                                                   + kc * 32 + (lane >> 4) * 16));
#pragma unroll
            for (int g = 0; g < 4; g++) {
                uint32_t vb[4];
                ldmatrix_x4_trans(vb, sb + SM_V
                    + (uint32_t)((kc * 16 + (lane & 15)) * 272
                                 + (wn * 64 + g * 16 + (lane >> 4) * 8) * 2));
                mma_fp16(oacc[2 * g + 0], pa, &vb[0]);
                mma_fp16(oacc[2 * g + 1], pa, &vb[2]);
            }
        }
        __syncthreads();   // S4
        buf ^= 1;
    }

    float li0 = 1.f / l0, li1 = 1.f / l1;
    size_t a0 = (rowbase + q0 + r0) * DIM + hoff + wn * 64;
    size_t a1 = (rowbase + q0 + r1) * DIM + hoff + wn * 64;
#pragma unroll
    for (int nb = 0; nb < 8; nb++) {
        int c = nb * 8 + 2 * (lane & 3);
        *(__half2*)(OAh + a0 + c) =
            __floats2half2_rn(oacc[nb][0] * li0, oacc[nb][1] * li0);
        *(__half2*)(OAh + a1 + c) =
            __floats2half2_rn(oacc[nb][2] * li1, oacc[nb][3] * li1);
    }
}

// ---------------- launch ----------------
extern "C" void kernel_launch(void* const* d_in, const int* in_sizes, int n_in,
                              void* d_out, int out_size)
{
    const float* enc  = (const float*)d_in[0];
    const float* dec  = (const float*)d_in[1];
    const float* W_kv = (const float*)d_in[2];
    const float* b_kv = (const float*)d_in[3];
    const float* W_q  = (const float*)d_in[4];
    const float* b_q  = (const float*)d_in[5];
    const float* W_o  = (const float*)d_in[6];
    const float* b_o  = (const float*)d_in[7];
    float* out = (float*)d_out;

    __half *p_X, *p_D, *p_Wkv, *p_Wq, *p_Wo, *p_K, *p_V, *p_Qh;
    cudaGetSymbolAddress((void**)&p_X,   g_X16);
    cudaGetSymbolAddress((void**)&p_D,   g_D16);
    cudaGetSymbolAddress((void**)&p_Wkv, g_Wkv);
    cudaGetSymbolAddress((void**)&p_Wq,  g_Wq);
    cudaGetSymbolAddress((void**)&p_Wo,  g_Wo);
    cudaGetSymbolAddress((void**)&p_K,   g_K16);
    cudaGetSymbolAddress((void**)&p_V,   g_V16);
    cudaGetSymbolAddress((void**)&p_Qh,  g_Qh);

    cudaFuncSetAttribute((const void*)gemm_tc_kernel<0>, cudaFuncAttributeMaxDynamicSharedMemorySize, GEMM_SMEM);
    cudaFuncSetAttribute((const void*)gemm_tc_kernel<1>, cudaFuncAttributeMaxDynamicSharedMemorySize, GEMM_SMEM);
    cudaFuncSetAttribute((const void*)gemm_tc_kernel<2>, cudaFuncAttributeMaxDynamicSharedMemorySize, GEMM_SMEM);
    cudaFuncSetAttribute(attn_tc_kernel, cudaFuncAttributeMaxDynamicSharedMemorySize, ATT_SMEM);

    // 1. convert everything to fp16 (one kernel)
    conv_all_kernel<<<(N_CONV_TOTAL + 255) / 256, 256>>>(
        enc, dec, W_kv, W_q, W_o, p_X, p_D, p_Wkv, p_Wq, p_Wo);

    // 2. GEMM kv -> K16/V16
    gemm_tc_kernel<1><<<dim3(KVDIM / 128, MROWS / 128), 256, GEMM_SMEM>>>(
        p_X, p_Wkv, b_kv, p_K, p_V, KVDIM);

    // 3. GEMM q -> scaled Qh
    gemm_tc_kernel<2><<<dim3(DIM / 128, MROWS / 128), 256, GEMM_SMEM>>>(
        p_D, p_Wq, b_q, p_Qh, nullptr, DIM);

    // 4. attention -> fp16 AO into g_X16 (enc16 no longer needed)
    attn_tc_kernel<<<dim3(TSEQ / 128, BATCH * NHEAD), 512, ATT_SMEM>>>(
        p_Qh, p_K, p_V, p_X);

    // 5. GEMM out (fp32)
    gemm_tc_kernel<0><<<dim3(DIM / 128, MROWS / 128), 256, GEMM_SMEM>>>(
        p_X, p_Wo, b_o, out, nullptr, DIM);
}

// round 16
// speedup vs baseline: 1.0558x; 1.0558x over previous
#include <cuda_runtime.h>
#include <cuda_fp16.h>
#include <cstdint>

#define TSEQ   2048
#define BATCH  4
#define NHEAD  16
#define HD     128
#define DIM    2048
#define MROWS  (BATCH * TSEQ)   // 8192
#define KVDIM  (2 * DIM)        // 4096

// ---------------- scratch (allocation-free: __device__ globals) ----------------
__device__ __half g_X16 [(size_t)MROWS * DIM];    // enc fp16, later attention output
__device__ __half g_D16 [(size_t)MROWS * DIM];    // dec fp16
__device__ __half g_Wkv [(size_t)DIM * KVDIM];    // fp16 W_kv, native [K,N]
__device__ __half g_Wq  [(size_t)DIM * DIM];
__device__ __half g_Wo  [(size_t)DIM * DIM];
__device__ __half g_K16 [(size_t)MROWS * DIM];
__device__ __half g_V16 [(size_t)MROWS * DIM];
__device__ __half g_Qh  [(size_t)MROWS * DIM];

// ---------------- helpers ----------------
__device__ __forceinline__ uint32_t smem_u32(const void* p) {
    uint32_t a;
    asm("{ .reg .u64 t; cvta.to.shared.u64 t, %1; cvt.u32.u64 %0, t; }"
        : "=r"(a) : "l"(p));
    return a;
}
#define CP_ASYNC16(dst, src) \
    asm volatile("cp.async.cg.shared.global [%0], [%1], 16;" :: "r"(dst), "l"(src))

__device__ __forceinline__ void ldmatrix_x4(uint32_t* r, uint32_t addr) {
    asm volatile("ldmatrix.sync.aligned.m8n8.x4.shared.b16 {%0,%1,%2,%3}, [%4];"
                 : "=r"(r[0]), "=r"(r[1]), "=r"(r[2]), "=r"(r[3]) : "r"(addr));
}
__device__ __forceinline__ void ldmatrix_x4_trans(uint32_t* r, uint32_t addr) {
    asm volatile("ldmatrix.sync.aligned.m8n8.x4.trans.shared.b16 {%0,%1,%2,%3}, [%4];"
                 : "=r"(r[0]), "=r"(r[1]), "=r"(r[2]), "=r"(r[3]) : "r"(addr));
}
__device__ __forceinline__ void sts32(uint32_t a, uint32_t v) {
    asm volatile("st.shared.b32 [%0], %1;" :: "r"(a), "r"(v));
}
__device__ __forceinline__ void mma_fp16(float* d, const uint32_t* a, const uint32_t* b) {
    asm volatile(
        "mma.sync.aligned.m16n8k16.row.col.f32.f16.f16.f32 "
        "{%0,%1,%2,%3}, {%4,%5,%6,%7}, {%8,%9}, {%0,%1,%2,%3};"
        : "+f"(d[0]), "+f"(d[1]), "+f"(d[2]), "+f"(d[3])
        : "r"(a[0]), "r"(a[1]), "r"(a[2]), "r"(a[3]), "r"(b[0]), "r"(b[1]));
}

// fast exp2 on FMA pipe (t <= ~0)
__device__ __forceinline__ float exp2p(float t) {
    t = fmaxf(t, -126.f);
    float fi = floorf(t);
    float x = t - fi - 0.5f;
    float p = 0.001885630f;
    p = fmaf(p, x, 0.013602145f);
    p = fmaf(p, x, 0.078494717f);
    p = fmaf(p, x, 0.339731669f);
    p = fmaf(p, x, 0.980258143f);
    p = fmaf(p, x, 1.414213562f);
    int e = (int)fi;
    return __int_as_float(__float_as_int(p) + (e << 23));
}

// ---------------- fused conversion (4 independent float4s per thread, MLP=4) ----------------
#define N_ACT (MROWS * DIM / 4)          // 4194304 float4
#define N_WKV (DIM * KVDIM / 4)          // 2097152
#define N_W   (DIM * DIM / 4)            // 1048576
#define N_CONV_TOTAL (2 * N_ACT + N_WKV + 2 * N_W)   // 12582912

__global__ __launch_bounds__(256) void conv_all_kernel(
    const float* __restrict__ enc, const float* __restrict__ dec,
    const float* __restrict__ wkv, const float* __restrict__ wq,
    const float* __restrict__ wo,
    __half* __restrict__ x16, __half* __restrict__ d16,
    __half* __restrict__ wkv16, __half* __restrict__ wq16,
    __half* __restrict__ wo16)
{
    const int t0 = blockIdx.x * 1024 + threadIdx.x;
    float4 v[4];
    __half* dstp[4];
    bool ok[4];
#pragma unroll
    for (int k = 0; k < 4; k++) {
        int i = t0 + k * 256;
        ok[k] = (i < N_CONV_TOTAL);
        const float* src; __half* dst; int off;
        if (i < N_ACT)                        { src = enc; dst = x16;   off = i; }
        else if (i < 2 * N_ACT)               { src = dec; dst = d16;   off = i - N_ACT; }
        else if (i < 2 * N_ACT + N_WKV)       { src = wkv; dst = wkv16; off = i - 2 * N_ACT; }
        else if (i < 2 * N_ACT + N_WKV + N_W) { src = wq;  dst = wq16;  off = i - 2 * N_ACT - N_WKV; }
        else                                  { src = wo;  dst = wo16;  off = i - 2 * N_ACT - N_WKV - N_W; }
        if (ok[k]) v[k] = ((const float4*)src)[off];
        dstp[k] = dst + (size_t)off * 4;
    }
#pragma unroll
    for (int k = 0; k < 4; k++) {
        if (!ok[k]) continue;
        __half2* hp = (__half2*)dstp[k];
        hp[0] = __floats2half2_rn(v[k].x, v[k].y);
        hp[1] = __floats2half2_rn(v[k].z, v[k].w);
    }
}

// ---------------- mma.sync GEMM core (shared by fused 1+2 and GEMM3) ----------------
#define BKG      64
#define ROWB     144
#define BROWB    272
#define ATILE_B  (128 * ROWB)              // 18432
#define BTILE_B  (64 * BROWB)              // 17408
#define BUF_B    (ATILE_B + BTILE_B)       // 35840
#define GEMM_SMEM (2 * BUF_B)              // 71680 -> 2 CTAs/SM
#define NCH 32

// mode 0: fp32 C = acc + bias; mode 1: fp16 K/V split; mode 2: fp16 scaled q
__device__ __forceinline__ void gemm_body(
    const __half* __restrict__ Ah, const __half* __restrict__ Wf,
    const float* __restrict__ bias, void* outA, void* outB, int N,
    int bm, int bn, int mode, char* smem)
{
    const uint32_t sbase = smem_u32(smem);
    const int tid  = threadIdx.x;
    const int wid  = tid >> 5;
    const int lane = tid & 31;
    const int wm   = wid & 1;
    const int wn   = wid >> 1;

    float acc[4][4][4];
#pragma unroll
    for (int i = 0; i < 4; i++)
#pragma unroll
        for (int j = 0; j < 4; j++)
#pragma unroll
            for (int k = 0; k < 4; k++) acc[i][j][k] = 0.f;

    const uint32_t a_lane_off = (uint32_t)((lane & 15) * ROWB + ((lane >> 4) << 3) * 2);
    const uint32_t a_warp_base = (uint32_t)(wm * 64) * ROWB;

    auto load_chunk = [&](int ci, int buf) {
        const int k0 = ci * BKG;
        const uint32_t base = sbase + (uint32_t)buf * BUF_B;
#pragma unroll
        for (int j = 0; j < 8; j++) {
            int c = j * 256 + tid;
            uint32_t dst;
            const __half* g;
            if (c < 1024) {
                int row = c >> 3, seg = c & 7;
                dst = base + (uint32_t)(row * ROWB + seg * 16);
                g = Ah + (size_t)(bm + row) * DIM + k0 + seg * 8;
            } else {
                int idx = c - 1024;
                int row = idx >> 4, seg = idx & 15;
                dst = base + (uint32_t)(ATILE_B + row * BROWB + seg * 16);
                g = Wf + (size_t)(k0 + row) * N + bn + seg * 8;
            }
            CP_ASYNC16(dst, g);
        }
        asm volatile("cp.async.commit_group;");
    };

    load_chunk(0, 0);

    for (int i = 0; i < NCH; i++) {
        const int b = i & 1;
        const bool has_next = (i + 1 < NCH);
        if (has_next) load_chunk(i + 1, b ^ 1);
        if (has_next) asm volatile("cp.async.wait_group 1;");
        else          asm volatile("cp.async.wait_group 0;");
        __syncthreads();

        const uint32_t abuf = sbase + (uint32_t)b * BUF_B;
        const uint32_t bbuf = abuf + ATILE_B;
#pragma unroll
        for (int ks = 0; ks < 4; ks++) {
            uint32_t afrag[4][4];
#pragma unroll
            for (int mf = 0; mf < 4; mf++)
                ldmatrix_x4(afrag[mf],
                            abuf + a_warp_base + (uint32_t)(mf * 16 * ROWB)
                                 + (uint32_t)(ks * 32) + a_lane_off);
            uint32_t bfrag[4][2];
#pragma unroll
            for (int p = 0; p < 2; p++) {
                uint32_t r4[4];
                ldmatrix_x4_trans(r4, bbuf
                    + (uint32_t)((ks * 16 + (lane & 15)) * BROWB
                                 + (wn * 32 + p * 16 + (lane >> 4) * 8) * 2));
                bfrag[2 * p + 0][0] = r4[0]; bfrag[2 * p + 0][1] = r4[1];
                bfrag[2 * p + 1][0] = r4[2]; bfrag[2 * p + 1][1] = r4[3];
            }
#pragma unroll
            for (int mf = 0; mf < 4; mf++)
#pragma unroll
                for (int nf = 0; nf < 4; nf++)
                    mma_fp16(acc[mf][nf], afrag[mf], bfrag[nf]);
        }
        __syncthreads();
    }

    // ---- epilogue ----
    const float CSCL = (float)(0.08838834764831845 * 1.4426950408889634);
    float2 bfr[4];
#pragma unroll
    for (int nf = 0; nf < 4; nf++) {
        int col = bn + wn * 32 + nf * 8 + (lane & 3) * 2;
        bfr[nf].x = __ldg(bias + col);
        bfr[nf].y = __ldg(bias + col + 1);
    }
#pragma unroll
    for (int mf = 0; mf < 4; mf++) {
#pragma unroll
        for (int h8 = 0; h8 < 2; h8++) {
            int row = bm + wm * 64 + mf * 16 + (lane >> 2) + h8 * 8;
#pragma unroll
            for (int nf = 0; nf < 4; nf++) {
                float vx = acc[mf][nf][2 * h8 + 0] + bfr[nf].x;
                float vy = acc[mf][nf][2 * h8 + 1] + bfr[nf].y;
                int coff = wn * 32 + nf * 8 + (lane & 3) * 2;
                if (mode == 0) {
                    float* C = (float*)outA;
                    float2 o; o.x = vx; o.y = vy;
                    *(float2*)(C + (size_t)row * N + bn + coff) = o;
                } else if (mode == 1) {
                    __half* dst = (bn < DIM) ? (__half*)outA : (__half*)outB;
                    int cb = (bn & (DIM - 1)) + coff;
                    *(__half2*)(dst + (size_t)row * DIM + cb) =
                        __floats2half2_rn(vx, vy);
                } else {
                    *(__half2*)((__half*)outA + (size_t)row * DIM + bn + coff) =
                        __floats2half2_rn(vx * CSCL, vy * CSCL);
                }
            }
        }
    }
}

// fused GEMM1 (kv) + GEMM2 (q): 2048 + 1024 = 3072 CTAs in one launch
__global__ __launch_bounds__(256, 2) void gemm12_kernel(
    const __half* __restrict__ X, const __half* __restrict__ D,
    const __half* __restrict__ Wkv, const __half* __restrict__ Wq,
    const float* __restrict__ b_kv, const float* __restrict__ b_q,
    __half* K16, __half* V16, __half* Qh)
{
    extern __shared__ char smem[];
    const int bid = blockIdx.x;
    if (bid < 2048) {
        int bx = bid & 31, by = bid >> 5;
        gemm_body(X, Wkv, b_kv, K16, V16, KVDIM, by * 128, bx * 128, 1, smem);
    } else {
        int id = bid - 2048;
        int bx = id & 15, by = id >> 4;
        gemm_body(D, Wq, b_q, Qh, nullptr, DIM, by * 128, bx * 128, 2, smem);
    }
}

// GEMM3: output projection (fp32 out)
__global__ __launch_bounds__(256, 2) void gemm3_kernel(
    const __half* __restrict__ AO, const __half* __restrict__ Wo,
    const float* __restrict__ b_o, float* out)
{
    extern __shared__ char smem[];
    gemm_body(AO, Wo, b_o, out, nullptr, DIM,
              blockIdx.y * 128, blockIdx.x * 128, 0, smem);
}

// ---------------- fp16 tensor-core flash attention (BM=64, 256 thr, 2 CTAs/SM) ----------------
#define SM_QH   0
#define SM_K0   17408
#define SM_K1   34816
#define SM_V    52224
#define SM_P    69632
#define SM_RMAX 78848
#define SM_RSUM 79360
#define ATT_SMEM 79872

__global__ __launch_bounds__(256, 2) void attn_tc_kernel(
    const __half* __restrict__ Qh,
    const __half* __restrict__ K16, const __half* __restrict__ V16,
    __half* __restrict__ OAh)
{
    extern __shared__ char smem[];
    const uint32_t sb = smem_u32(smem);
    const int tid = threadIdx.x, lane = tid & 31, wid = tid >> 5;
    const int wm = wid & 3, wn = wid >> 2;
    const int qt = (int)gridDim.x - 1 - (int)blockIdx.x;
    const int bh = blockIdx.y, bb = bh >> 4, hh = bh & 15;
    const int q0 = qt * 64;
    const size_t rowbase = (size_t)bb * TSEQ;
    const int hoff = hh * HD;

    float* sRMax = (float*)(smem + SM_RMAX);
    float* sRSum = (float*)(smem + SM_RSUM);

#pragma unroll
    for (int it = 0; it < 4; it++) {
        int idx = tid + it * 256; int r = idx >> 4, sg = idx & 15;
        CP_ASYNC16(sb + SM_QH + r * 272 + sg * 16,
                   Qh + (rowbase + q0 + r) * DIM + hoff + sg * 8);
    }
    asm volatile("cp.async.commit_group;");

    auto loadK = [&](int j0, uint32_t base) {
#pragma unroll
        for (int it = 0; it < 4; it++) {
            int idx = tid + it * 256; int r = idx >> 4, sg = idx & 15;
            CP_ASYNC16(base + r * 272 + sg * 16,
                       K16 + (rowbase + j0 + r) * DIM + hoff + sg * 8);
        }
        asm volatile("cp.async.commit_group;");
    };
    auto loadV = [&](int j0) {
#pragma unroll
        for (int it = 0; it < 4; it++) {
            int idx = tid + it * 256; int r = idx >> 4, sg = idx & 15;
            CP_ASYNC16(sb + SM_V + r * 272 + sg * 16,
                       V16 + (rowbase + j0 + r) * DIM + hoff + sg * 8);
        }
        asm volatile("cp.async.commit_group;");
    };

    loadK(0, sb + SM_K0);

    float oacc[8][4];
#pragma unroll
    for (int i = 0; i < 8; i++)
#pragma unroll
        for (int k = 0; k < 4; k++) oacc[i][k] = 0.f;
    float m0 = -1e9f, m1 = -1e9f, l0 = 0.f, l1 = 0.f;

    const int r0 = wm * 16 + (lane >> 2);
    const int r1 = r0 + 8;
    int buf = 0;

    for (int j = 0; j <= qt; j++) {
        const int j0 = j * 64;
        loadV(j0);
        if (j < qt) loadK(j0 + 64, sb + (buf ? SM_K0 : SM_K1));
        if (j < qt) asm volatile("cp.async.wait_group 2;");
        else        asm volatile("cp.async.wait_group 1;");
        __syncthreads();   // S1

        const uint32_t kb = sb + (buf ? SM_K1 : SM_K0);
        float sacc[4][4];
#pragma unroll
        for (int nf = 0; nf < 4; nf++)
#pragma unroll
            for (int e = 0; e < 4; e++) sacc[nf][e] = 0.f;

#pragma unroll
        for (int kc = 0; kc < 8; kc++) {
            uint32_t bbf[4][2];
#pragma unroll
            for (int p = 0; p < 2; p++) {
                uint32_t r4[4];
                int g = lane >> 3, r = lane & 7;
                ldmatrix_x4(r4, kb + (uint32_t)(
                    (wn * 32 + p * 16 + ((g >> 1) << 3) + r) * 272
                    + kc * 32 + ((g & 1) << 4)));
                bbf[2 * p + 0][0] = r4[0]; bbf[2 * p + 0][1] = r4[1];
                bbf[2 * p + 1][0] = r4[2]; bbf[2 * p + 1][1] = r4[3];
            }
            uint32_t qa = (uint32_t)((wm * 16 + (lane & 15)) * 272
                                     + kc * 32 + (lane >> 4) * 16);
            uint32_t ah[4];
            ldmatrix_x4(ah, sb + SM_QH + qa);
#pragma unroll
            for (int nf = 0; nf < 4; nf++)
                mma_fp16(sacc[nf], ah, bbf[nf]);
        }

        if (j == qt) {
#pragma unroll
            for (int nf = 0; nf < 4; nf++)
#pragma unroll
                for (int e = 0; e < 4; e++) {
                    int col = j0 + wn * 32 + nf * 8 + 2 * (lane & 3) + (e & 1);
                    int row = q0 + ((e >> 1) ? r1 : r0);
                    if (col > row) sacc[nf][e] = -1e9f;
                }
        }

        float mx0 = -1e30f, mx1 = -1e30f;
#pragma unroll
        for (int nf = 0; nf < 4; nf++) {
            mx0 = fmaxf(mx0, fmaxf(sacc[nf][0], sacc[nf][1]));
            mx1 = fmaxf(mx1, fmaxf(sacc[nf][2], sacc[nf][3]));
        }
        mx0 = fmaxf(mx0, __shfl_xor_sync(0xffffffffu, mx0, 1));
        mx0 = fmaxf(mx0, __shfl_xor_sync(0xffffffffu, mx0, 2));
        mx1 = fmaxf(mx1, __shfl_xor_sync(0xffffffffu, mx1, 1));
        mx1 = fmaxf(mx1, __shfl_xor_sync(0xffffffffu, mx1, 2));
        if ((lane & 3) == 0) {
            sRMax[r0 * 2 + wn] = mx0;
            sRMax[r1 * 2 + wn] = mx1;
        }
        __syncthreads();   // S2

        float nm0 = fmaxf(m0, fmaxf(sRMax[r0 * 2], sRMax[r0 * 2 + 1]));
        float nm1 = fmaxf(m1, fmaxf(sRMax[r1 * 2], sRMax[r1 * 2 + 1]));
        float alpha0 = exp2p(m0 - nm0);
        float alpha1 = exp2p(m1 - nm1);
        m0 = nm0; m1 = nm1;

        float s0 = 0.f, s1 = 0.f;
        uint32_t pbase = sb + SM_P + (uint32_t)((wm * 16 + (lane >> 2)) * 144
                                                + wn * 64 + (lane & 3) * 4);
#pragma unroll
        for (int nf = 0; nf < 4; nf++) {
            float p0 = exp2p(sacc[nf][0] - m0);
            float p1 = exp2p(sacc[nf][1] - m0);
            float p2 = exp2p(sacc[nf][2] - m1);
            float p3 = exp2p(sacc[nf][3] - m1);
            s0 += p0 + p1; s1 += p2 + p3;
            __half2 hp0 = __floats2half2_rn(p0, p1);
            __half2 hp1 = __floats2half2_rn(p2, p3);
            sts32(pbase + nf * 16,           *(uint32_t*)&hp0);
            sts32(pbase + nf * 16 + 8 * 144, *(uint32_t*)&hp1);
        }
        s0 += __shfl_xor_sync(0xffffffffu, s0, 1);
        s0 += __shfl_xor_sync(0xffffffffu, s0, 2);
        s1 += __shfl_xor_sync(0xffffffffu, s1, 1);
        s1 += __shfl_xor_sync(0xffffffffu, s1, 2);
        if ((lane & 3) == 0) {
            sRSum[r0 * 2 + wn] = s0;
            sRSum[r1 * 2 + wn] = s1;
        }

#pragma unroll
        for (int nb = 0; nb < 8; nb++) {
            oacc[nb][0] *= alpha0; oacc[nb][1] *= alpha0;
            oacc[nb][2] *= alpha1; oacc[nb][3] *= alpha1;
        }

        if (j < qt) asm volatile("cp.async.wait_group 1;");
        else        asm volatile("cp.async.wait_group 0;");
        __syncthreads();   // S3

        l0 = l0 * alpha0 + sRSum[r0 * 2] + sRSum[r0 * 2 + 1];
        l1 = l1 * alpha1 + sRSum[r1 * 2] + sRSum[r1 * 2 + 1];

#pragma unroll
        for (int kc = 0; kc < 4; kc++) {
            uint32_t pa[4];
            ldmatrix_x4(pa, sb + SM_P + (uint32_t)((wm * 16 + (lane & 15)) * 144
                                                   + kc * 32 + (lane >> 4) * 16));
#pragma unroll
            for (int g = 0; g < 4; g++) {
                uint32_t vb[4];
                ldmatrix_x4_trans(vb, sb + SM_V
                    + (uint32_t)((kc * 16 + (lane & 15)) * 272
                                 + (wn * 64 + g * 16 + (lane >> 4) * 8) * 2));
                mma_fp16(oacc[2 * g + 0], pa, &vb[0]);
                mma_fp16(oacc[2 * g + 1], pa, &vb[2]);
            }
        }
        __syncthreads();   // S4
        buf ^= 1;
    }

    float li0 = 1.f / l0, li1 = 1.f / l1;
    size_t a0 = (rowbase + q0 + r0) * DIM + hoff + wn * 64;
    size_t a1 = (rowbase + q0 + r1) * DIM + hoff + wn * 64;
#pragma unroll
    for (int nb = 0; nb < 8; nb++) {
        int c = nb * 8 + 2 * (lane & 3);
        *(__half2*)(OAh + a0 + c) =
            __floats2half2_rn(oacc[nb][0] * li0, oacc[nb][1] * li0);
        *(__half2*)(OAh + a1 + c) =
            __floats2half2_rn(oacc[nb][2] * li1, oacc[nb][3] * li1);
    }
}

// ---------------- launch ----------------
extern "C" void kernel_launch(void* const* d_in, const int* in_sizes, int n_in,
                              void* d_out, int out_size)
{
    const float* enc  = (const float*)d_in[0];
    const float* dec  = (const float*)d_in[1];
    const float* W_kv = (const float*)d_in[2];
    const float* b_kv = (const float*)d_in[3];
    const float* W_q  = (const float*)d_in[4];
    const float* b_q  = (const float*)d_in[5];
    const float* W_o  = (const float*)d_in[6];
    const float* b_o  = (const float*)d_in[7];
    float* out = (float*)d_out;

    __half *p_X, *p_D, *p_Wkv, *p_Wq, *p_Wo, *p_K, *p_V, *p_Qh;
    cudaGetSymbolAddress((void**)&p_X,   g_X16);
    cudaGetSymbolAddress((void**)&p_D,   g_D16);
    cudaGetSymbolAddress((void**)&p_Wkv, g_Wkv);
    cudaGetSymbolAddress((void**)&p_Wq,  g_Wq);
    cudaGetSymbolAddress((void**)&p_Wo,  g_Wo);
    cudaGetSymbolAddress((void**)&p_K,   g_K16);
    cudaGetSymbolAddress((void**)&p_V,   g_V16);
    cudaGetSymbolAddress((void**)&p_Qh,  g_Qh);

    cudaFuncSetAttribute(gemm12_kernel, cudaFuncAttributeMaxDynamicSharedMemorySize, GEMM_SMEM);
    cudaFuncSetAttribute(gemm3_kernel,  cudaFuncAttributeMaxDynamicSharedMemorySize, GEMM_SMEM);
    cudaFuncSetAttribute(attn_tc_kernel, cudaFuncAttributeMaxDynamicSharedMemorySize, ATT_SMEM);

    // 1. convert everything to fp16 (one kernel, MLP=4)
    conv_all_kernel<<<(N_CONV_TOTAL + 1023) / 1024, 256>>>(
        enc, dec, W_kv, W_q, W_o, p_X, p_D, p_Wkv, p_Wq, p_Wo);

    // 2. fused GEMM kv + q  (3072 CTAs)
    gemm12_kernel<<<3072, 256, GEMM_SMEM>>>(
        p_X, p_D, p_Wkv, p_Wq, b_kv, b_q, p_K, p_V, p_Qh);

    // 3. attention -> fp16 AO into g_X16
    attn_tc_kernel<<<dim3(TSEQ / 64, BATCH * NHEAD), 256, ATT_SMEM>>>(
        p_Qh, p_K, p_V, p_X);

    // 4. GEMM out (fp32)
    gemm3_kernel<<<dim3(DIM / 128, MROWS / 128), 256, GEMM_SMEM>>>(
        p_X, p_Wo, b_o, out);
}